// round 2
// baseline (speedup 1.0000x reference)
#include <cuda_runtime.h>
#include <math.h>

#define N_NODES 4096
#define D_INF   128
#define HD      128
#define HEADS   4
#define E_EDGES 131072
#define ET      (E_EDGES + N_NODES)     /* 135168 edges incl. self loops */
#define NG      (4*HD)                  /* 512 gates */
#define NEG_SLOPE 0.2f

/* ------------------------- scratch (device globals) ------------------------- */
__device__ float        g_h    [(size_t)N_NODES*NG];   /* GAT gemm out (N,4,128) */
__device__ float        g_asrc [N_NODES*HEADS];
__device__ float        g_adst [N_NODES*HEADS];
__device__ unsigned int g_menc [N_NODES*HEADS];
__device__ float        g_s    [N_NODES*HEADS];
__device__ float        g_aggr [(size_t)N_NODES*HD];   /* head-mean-folded agg */
__device__ float        g_g    [(size_t)N_NODES*HD];   /* GAT output (relu) */
__device__ float        g_xproj[(size_t)N_NODES*NG];   /* W_ih@x + b_ih + b_hh */
__device__ float        g_bias2[NG];
__device__ float        g_xn   [(size_t)N_NODES*HD];   /* normalized emb */

/* ------------------------------- helpers ------------------------------------ */
union U64F2 { unsigned long long u; float2 f; };

#define FMA2(d,a,b) asm("fma.rn.f32x2 %0, %1, %2, %0;" : "+l"(d) : "l"(a), "l"(b))

__device__ __forceinline__ float lrelu(float x){ return x > 0.f ? x : NEG_SLOPE*x; }

__device__ __forceinline__ unsigned enc_f(float v){
    unsigned u = __float_as_uint(v);
    return (u & 0x80000000u) ? ~u : (u | 0x80000000u);
}
__device__ __forceinline__ float dec_f(unsigned e){
    unsigned u = (e & 0x80000000u) ? (e & 0x7FFFFFFFu) : ~e;
    return __uint_as_float(u);
}
__device__ __forceinline__ void edge_nodes(const int* __restrict__ ei, int e, int& s, int& d){
    if (e < E_EDGES){ s = ei[e]; d = ei[E_EDGES + e]; }
    else            { s = e - E_EDGES; d = s; }
}
__device__ __forceinline__ float fsigm(float x){ return 1.f/(1.f + __expf(-x)); }
__device__ __forceinline__ float ftanh_(float x){
    x = fminf(fmaxf(x, -15.f), 15.f);
    float e = __expf(-2.f*x);
    return (1.f - e)/(1.f + e);
}

/* ------------------------------ init ---------------------------------------- */
__global__ void k_init(){
    int i = blockIdx.x*blockDim.x + threadIdx.x;
    if (i < N_NODES*HEADS){ g_menc[i] = 0u; g_s[i] = 0.f; }
    if (i < N_NODES*HD)    g_aggr[i] = 0.f;
}

/* ------------------------ generic 64x64 fp32 GEMM --------------------------- */
/* A: MxK row-major. transB=0: B is KxN row-major. transB=1: B is NxK row-major.
   M,N multiple of 64; K multiple of 16. */
__device__ __forceinline__ void sgemm_body(
    const float* __restrict__ A, const float* __restrict__ B, float* __restrict__ C,
    int M, int N, int K, const float* __restrict__ bias, int transB)
{
    __shared__ float As[16][64];
    __shared__ float Bs[16][64];
    const int tid  = threadIdx.x;                 /* 256 threads */
    const int brow = blockIdx.y*64, bcol = blockIdx.x*64;
    const int tx = tid & 15, ty = tid >> 4;
    const int lr = tid >> 2, lc = (tid & 3) << 2;
    float acc[4][4] = {};
    for (int k0 = 0; k0 < K; k0 += 16){
        float4 av = *(const float4*)(A + (size_t)(brow+lr)*K + k0 + lc);
        As[lc+0][lr]=av.x; As[lc+1][lr]=av.y; As[lc+2][lr]=av.z; As[lc+3][lr]=av.w;
        if (transB){
            float4 bv = *(const float4*)(B + (size_t)(bcol+lr)*K + k0 + lc);
            Bs[lc+0][lr]=bv.x; Bs[lc+1][lr]=bv.y; Bs[lc+2][lr]=bv.z; Bs[lc+3][lr]=bv.w;
        } else {
            const int br = tid >> 4, bc = (tid & 15) << 2;
            *(float4*)&Bs[br][bc] = *(const float4*)(B + (size_t)(k0+br)*N + bcol + bc);
        }
        __syncthreads();
        #pragma unroll
        for (int kk = 0; kk < 16; kk++){
            float4 rm4 = *(const float4*)&As[kk][ty<<2];
            float4 rn4 = *(const float4*)&Bs[kk][tx<<2];
            float rm[4] = {rm4.x, rm4.y, rm4.z, rm4.w};
            float rn[4] = {rn4.x, rn4.y, rn4.z, rn4.w};
            #pragma unroll
            for (int m = 0; m < 4; m++)
                #pragma unroll
                for (int n = 0; n < 4; n++)
                    acc[m][n] = fmaf(rm[m], rn[n], acc[m][n]);
        }
        __syncthreads();
    }
    #pragma unroll
    for (int m = 0; m < 4; m++){
        int row  = brow + (ty<<2) + m;
        int col0 = bcol + (tx<<2);
        float4 o;
        o.x = acc[m][0]; o.y = acc[m][1]; o.z = acc[m][2]; o.w = acc[m][3];
        if (bias){ o.x += bias[col0]; o.y += bias[col0+1]; o.z += bias[col0+2]; o.w += bias[col0+3]; }
        *(float4*)(C + (size_t)row*N + col0) = o;
    }
}

__global__ void __launch_bounds__(256) k_gemm_h(const float* __restrict__ x, const float* __restrict__ Wg){
    sgemm_body(x, Wg, g_h, N_NODES, NG, D_INF, nullptr, 0);
}
__global__ void __launch_bounds__(256) k_gemm_xp(const float* __restrict__ Wih){
    sgemm_body(g_g, Wih, g_xproj, N_NODES, NG, HD, g_bias2, 1);
}
__global__ void __launch_bounds__(256) k_gemm_corr(float* __restrict__ out_corr){
    sgemm_body(g_xn, g_xn, out_corr, N_NODES, N_NODES, HD, nullptr, 1);
}

/* ------------------------ attention scalars a_src/a_dst --------------------- */
__global__ void k_attn(const float* __restrict__ att_src, const float* __restrict__ att_dst){
    int gt = blockIdx.x*blockDim.x + threadIdx.x;
    int w = gt >> 5, lane = gt & 31;
    if (w >= N_NODES*HEADS) return;
    int n = w >> 2, hh = w & 3;
    const float* hp = g_h + (size_t)n*NG + hh*HD;
    const float* as = att_src + hh*HD;
    const float* ad = att_dst + hh*HD;
    float s1 = 0.f, s2 = 0.f;
    #pragma unroll
    for (int q = 0; q < 4; q++){
        int dd = lane + q*32;
        float v = hp[dd];
        s1 = fmaf(v, as[dd], s1);
        s2 = fmaf(v, ad[dd], s2);
    }
    #pragma unroll
    for (int o = 16; o; o >>= 1){
        s1 += __shfl_xor_sync(0xffffffffu, s1, o);
        s2 += __shfl_xor_sync(0xffffffffu, s2, o);
    }
    if (lane == 0){ g_asrc[w] = s1; g_adst[w] = s2; }
}

/* ------------------------------ edge softmax -------------------------------- */
__global__ void k_edge_max(const int* __restrict__ ei){
    int i = blockIdx.x*blockDim.x + threadIdx.x;
    if (i >= ET*HEADS) return;
    int e = i >> 2, hh = i & 3;
    int s, d; edge_nodes(ei, e, s, d);
    float v = lrelu(g_asrc[s*HEADS+hh] + g_adst[d*HEADS+hh]);
    atomicMax(&g_menc[d*HEADS+hh], enc_f(v));
}
__global__ void k_edge_sum(const int* __restrict__ ei){
    int i = blockIdx.x*blockDim.x + threadIdx.x;
    if (i >= ET*HEADS) return;
    int e = i >> 2, hh = i & 3;
    int s, d; edge_nodes(ei, e, s, d);
    int idx = d*HEADS + hh;
    float v = lrelu(g_asrc[s*HEADS+hh] + g_adst[idx]);
    atomicAdd(&g_s[idx], __expf(v - dec_f(g_menc[idx])));
}
/* one warp per edge; mean-over-heads folded in (alpha * 0.25) */
__global__ void k_edge_agg(const int* __restrict__ ei){
    int gt = blockIdx.x*blockDim.x + threadIdx.x;
    int w = gt >> 5, lane = gt & 31;
    if (w >= ET) return;
    int s, d; edge_nodes(ei, w, s, d);
    float alpha[HEADS];
    #pragma unroll
    for (int hh = 0; hh < HEADS; hh++){
        float v = lrelu(g_asrc[s*HEADS+hh] + g_adst[d*HEADS+hh]);
        int idx = d*HEADS + hh;
        alpha[hh] = __expf(v - dec_f(g_menc[idx])) / (g_s[idx] + 1e-16f) * 0.25f;
    }
    const float* hpv = g_h + (size_t)s*NG;
    float* op = g_aggr + (size_t)d*HD;
    #pragma unroll
    for (int q = 0; q < 4; q++){
        int dd = lane + q*32;
        float val = alpha[0]*hpv[dd] + alpha[1]*hpv[HD+dd]
                  + alpha[2]*hpv[2*HD+dd] + alpha[3]*hpv[3*HD+dd];
        atomicAdd(op + dd, val);
    }
}
__global__ void k_gat_fin(const float* __restrict__ b_gat){
    int i = blockIdx.x*blockDim.x + threadIdx.x;
    if (i < N_NODES*HD) g_g[i] = fmaxf(g_aggr[i] + b_gat[i & (HD-1)], 0.f);
}
__global__ void k_bias2(const float* __restrict__ bi, const float* __restrict__ bh){
    int i = blockIdx.x*blockDim.x + threadIdx.x;
    if (i < NG) g_bias2[i] = bi[i] + bh[i];
}

/* ------------------------------ LSTM (sequential) --------------------------- */
/* 1024 threads, 1 block. Thread tid: gate r = tid>>1, half = tid&1 owns
   64 W_hh weights (32 packed f32x2 in registers). h broadcast via smem. */
__global__ void __launch_bounds__(1024,1) k_lstm(const float* __restrict__ W_hh,
                                                 float* __restrict__ out_emb)
{
    __shared__ __align__(16) float h_sh[HD];
    __shared__ float gates[NG];
    const int tid  = threadIdx.x;
    const int r    = tid >> 1;
    const int half = tid & 1;

    unsigned long long wv[32];
    const unsigned long long* wp =
        (const unsigned long long*)(W_hh + (size_t)r*HD + half*64);
    #pragma unroll
    for (int i = 0; i < 32; i++) wv[i] = wp[i];

    if (tid < HD) h_sh[tid] = 0.f;
    float cst = 0.f;
    float xp  = g_xproj[r];          /* row t=0 (bias pre-folded by GEMM) */
    const unsigned long long* hp = (const unsigned long long*)h_sh + half*32;
    __syncthreads();

    for (int t = 0; t < N_NODES; t++){
        unsigned long long a0=0ull, a1=0ull, a2=0ull, a3=0ull;
        #pragma unroll
        for (int i = 0; i < 32; i += 4){
            unsigned long long h0 = hp[i+0], h1 = hp[i+1], h2 = hp[i+2], h3 = hp[i+3];
            FMA2(a0, wv[i+0], h0);
            FMA2(a1, wv[i+1], h1);
            FMA2(a2, wv[i+2], h2);
            FMA2(a3, wv[i+3], h3);
        }
        U64F2 u0, u1, u2, u3; u0.u=a0; u1.u=a1; u2.u=a2; u3.u=a3;
        float ssum = ((u0.f.x+u0.f.y)+(u1.f.x+u1.f.y))
                   + ((u2.f.x+u2.f.y)+(u3.f.x+u3.f.y));
        ssum += __shfl_xor_sync(0xffffffffu, ssum, 1);
        float gate = xp + ssum;
        if (!half) gates[r] = gate;
        if (t+1 < N_NODES) xp = __ldg(&g_xproj[(size_t)(t+1)*NG + r]);  /* prefetch */
        __syncthreads();
        if (tid < HD){
            float gi = gates[tid];
            float gf = gates[HD   + tid];
            float gg = gates[2*HD + tid];
            float go = gates[3*HD + tid];
            cst = fsigm(gf)*cst + fsigm(gi)*ftanh_(gg);
            float hn = fsigm(go)*ftanh_(cst);
            h_sh[tid] = hn;
            out_emb[(size_t)t*HD + tid] = hn;
        }
        __syncthreads();
    }
}

/* ------------------------------ normalize ----------------------------------- */
__global__ void k_norm(const float* __restrict__ emb){
    __shared__ float red[4];
    int t = blockIdx.x, d = threadIdx.x;       /* 128 threads */
    float v  = emb[(size_t)t*HD + d];
    float ss = v*v;
    #pragma unroll
    for (int o = 16; o; o >>= 1) ss += __shfl_xor_sync(0xffffffffu, ss, o);
    if ((d & 31) == 0) red[d >> 5] = ss;
    __syncthreads();
    float tot = red[0] + red[1] + red[2] + red[3];
    float inv = 1.f / fmaxf(sqrtf(tot), 1e-12f);
    g_xn[(size_t)t*HD + d] = v * inv;
}

/* --------------------------------- MLP -------------------------------------- */
__global__ void k_mlp(const float* __restrict__ emb,
                      const float* __restrict__ W1, const float* __restrict__ b1,
                      const float* __restrict__ W2, const float* __restrict__ b2,
                      float* __restrict__ mu, float* __restrict__ sg)
{
    __shared__ float xs[HD];
    __shared__ float hid[32];
    int t = blockIdx.x, tid = threadIdx.x;     /* 128 threads */
    xs[tid] = emb[(size_t)t*HD + tid];
    __syncthreads();
    if (tid < 32){
        float a = b1[tid];
        #pragma unroll 8
        for (int k = 0; k < HD; k++) a = fmaf(xs[k], W1[k*32 + tid], a);
        hid[tid] = fmaxf(a, 0.f);
    }
    __syncthreads();
    if (tid < 2){
        float a = b2[tid];
        #pragma unroll
        for (int k = 0; k < 32; k++) a = fmaf(hid[k], W2[k*2 + tid], a);
        if (tid == 0) mu[t] = a; else sg[t] = a;
    }
}

/* ------------------------------ launch -------------------------------------- */
extern "C" void kernel_launch(void* const* d_in, const int* in_sizes, int n_in,
                              void* d_out, int out_size)
{
    const float* x       = (const float*)d_in[0];
    const int*   ei      = (const int*  )d_in[1];
    const float* W_gat   = (const float*)d_in[2];
    const float* att_src = (const float*)d_in[3];
    const float* att_dst = (const float*)d_in[4];
    const float* b_gat   = (const float*)d_in[5];
    const float* W_ih    = (const float*)d_in[6];
    const float* W_hh    = (const float*)d_in[7];
    const float* b_ih    = (const float*)d_in[8];
    const float* b_hh    = (const float*)d_in[9];
    const float* W1      = (const float*)d_in[10];
    const float* b1      = (const float*)d_in[11];
    const float* W2      = (const float*)d_in[12];
    const float* b2      = (const float*)d_in[13];

    float* out      = (float*)d_out;
    float* out_emb  = out;
    float* out_corr = out + (size_t)N_NODES*HD;
    float* out_mu   = out_corr + (size_t)N_NODES*N_NODES;
    float* out_sg   = out_mu + N_NODES;

    k_init    <<<(N_NODES*HD + 255)/256, 256>>>();
    k_gemm_h  <<<dim3(NG/64, N_NODES/64), 256>>>(x, W_gat);
    k_attn    <<<(N_NODES*HEADS*32 + 255)/256, 256>>>(att_src, att_dst);
    k_edge_max<<<(ET*HEADS + 255)/256, 256>>>(ei);
    k_edge_sum<<<(ET*HEADS + 255)/256, 256>>>(ei);
    k_edge_agg<<<(ET*32    + 255)/256, 256>>>(ei);
    k_gat_fin <<<(N_NODES*HD + 255)/256, 256>>>(b_gat);
    k_bias2   <<<2, 256>>>(b_ih, b_hh);
    k_gemm_xp <<<dim3(NG/64, N_NODES/64), 256>>>(W_ih);
    k_lstm    <<<1, 1024>>>(W_hh, out_emb);
    k_norm    <<<N_NODES, HD>>>(out_emb);
    k_gemm_corr<<<dim3(N_NODES/64, N_NODES/64), 256>>>(out_corr);
    k_mlp     <<<N_NODES, HD>>>(out_emb, W1, b1, W2, b2, out_mu, out_sg);
}

// round 7
// speedup vs baseline: 1.4624x; 1.4624x over previous
#include <cuda_runtime.h>
#include <cstdint>
#include <math.h>

#define N_NODES 4096
#define D_INF   128
#define HD      128
#define HEADS   4
#define E_EDGES 131072
#define ET      (E_EDGES + N_NODES)     /* 135168 edges incl. self loops */
#define NG      (4*HD)                  /* 512 gates */
#define NEG_SLOPE 0.2f

/* ------------------------- scratch (device globals) ------------------------- */
__device__ float        g_h    [(size_t)N_NODES*NG];   /* GAT gemm out (N,4,128) */
__device__ float        g_asrc [N_NODES*HEADS];
__device__ float        g_adst [N_NODES*HEADS];
__device__ unsigned int g_menc [N_NODES*HEADS];
__device__ float        g_s    [N_NODES*HEADS];
__device__ float        g_aggr [(size_t)N_NODES*HD];   /* head-mean-folded agg */
__device__ float        g_g    [(size_t)N_NODES*HD];   /* GAT output (relu) */
__device__ float        g_xproj[(size_t)N_NODES*NG];   /* W_ih@x + b_ih + b_hh */
__device__ float        g_bias2[NG];
__device__ float        g_xn   [(size_t)N_NODES*HD];   /* normalized emb */

/* ------------------------------- helpers ------------------------------------ */
union U64F2 { unsigned long long u; float2 f; };

#define FMA2(d,a,b) asm("fma.rn.f32x2 %0, %1, %2, %0;" : "+l"(d) : "l"(a), "l"(b))

__device__ __forceinline__ float lrelu(float x){ return x > 0.f ? x : NEG_SLOPE*x; }

__device__ __forceinline__ unsigned enc_f(float v){
    unsigned u = __float_as_uint(v);
    return (u & 0x80000000u) ? ~u : (u | 0x80000000u);
}
__device__ __forceinline__ float dec_f(unsigned e){
    unsigned u = (e & 0x80000000u) ? (e & 0x7FFFFFFFu) : ~e;
    return __uint_as_float(u);
}
__device__ __forceinline__ void edge_nodes(const int* __restrict__ ei, int e, int& s, int& d){
    if (e < E_EDGES){ s = ei[e]; d = ei[E_EDGES + e]; }
    else            { s = e - E_EDGES; d = s; }
}
__device__ __forceinline__ float fsigm(float x){ return 1.f/(1.f + __expf(-x)); }
__device__ __forceinline__ float ftanh_(float x){
    x = fminf(fmaxf(x, -15.f), 15.f);
    float e = __expf(-2.f*x);
    return (1.f - e)/(1.f + e);
}

/* ---------------------- cluster / mbarrier PTX helpers ---------------------- */
__device__ __forceinline__ uint32_t smem_u32(const void* p){
    return (uint32_t)__cvta_generic_to_shared(p);
}
__device__ __forceinline__ uint32_t ctarank(){
    uint32_t r; asm("mov.u32 %0, %%cluster_ctarank;" : "=r"(r)); return r;
}
__device__ __forceinline__ uint32_t mapa_rank(uint32_t a, uint32_t rank){
    uint32_t r; asm("mapa.shared::cluster.u32 %0, %1, %2;" : "=r"(r) : "r"(a), "r"(rank));
    return r;
}
__device__ __forceinline__ void st_cluster_f32(uint32_t a, float v){
    asm volatile("st.shared::cluster.f32 [%0], %1;" :: "r"(a), "f"(v) : "memory");
}
__device__ __forceinline__ void mbar_init(uint32_t a, uint32_t cnt){
    asm volatile("mbarrier.init.shared.b64 [%0], %1;" :: "r"(a), "r"(cnt) : "memory");
}
__device__ __forceinline__ void mbar_arrive_rel_cluster(uint32_t a){
    asm volatile("mbarrier.arrive.release.cluster.shared::cluster.b64 _, [%0];"
                 :: "r"(a) : "memory");
}
__device__ __forceinline__ void mbar_wait_acq_cluster(uint32_t a, uint32_t ph){
    uint32_t done;
    asm volatile("{\n\t.reg .pred p;\n\t"
                 "mbarrier.try_wait.parity.acquire.cluster.shared::cta.b64 p, [%1], %2;\n\t"
                 "selp.b32 %0, 1, 0, p;\n\t}"
                 : "=r"(done) : "r"(a), "r"(ph) : "memory");
    while (!done){
        asm volatile("{\n\t.reg .pred p;\n\t"
                     "mbarrier.try_wait.parity.acquire.cluster.shared::cta.b64 p, [%1], %2, 0x989680;\n\t"
                     "selp.b32 %0, 1, 0, p;\n\t}"
                     : "=r"(done) : "r"(a), "r"(ph) : "memory");
    }
}
__device__ __forceinline__ void cluster_sync_(){
    asm volatile("barrier.cluster.arrive.aligned;" ::: "memory");
    asm volatile("barrier.cluster.wait.aligned;" ::: "memory");
}

/* ------------------------------ init ---------------------------------------- */
__global__ void k_init(){
    int i = blockIdx.x*blockDim.x + threadIdx.x;
    if (i < N_NODES*HEADS){ g_menc[i] = 0u; g_s[i] = 0.f; }
    if (i < N_NODES*HD)    g_aggr[i] = 0.f;
}

/* ------------------------ generic 64x64 fp32 GEMM --------------------------- */
__device__ __forceinline__ void sgemm_body(
    const float* __restrict__ A, const float* __restrict__ B, float* __restrict__ C,
    int M, int N, int K, const float* __restrict__ bias, int transB)
{
    __shared__ float As[16][64];
    __shared__ float Bs[16][64];
    const int tid  = threadIdx.x;                 /* 256 threads */
    const int brow = blockIdx.y*64, bcol = blockIdx.x*64;
    const int tx = tid & 15, ty = tid >> 4;
    const int lr = tid >> 2, lc = (tid & 3) << 2;
    float acc[4][4] = {};
    for (int k0 = 0; k0 < K; k0 += 16){
        float4 av = *(const float4*)(A + (size_t)(brow+lr)*K + k0 + lc);
        As[lc+0][lr]=av.x; As[lc+1][lr]=av.y; As[lc+2][lr]=av.z; As[lc+3][lr]=av.w;
        if (transB){
            float4 bv = *(const float4*)(B + (size_t)(bcol+lr)*K + k0 + lc);
            Bs[lc+0][lr]=bv.x; Bs[lc+1][lr]=bv.y; Bs[lc+2][lr]=bv.z; Bs[lc+3][lr]=bv.w;
        } else {
            const int br = tid >> 4, bc = (tid & 15) << 2;
            *(float4*)&Bs[br][bc] = *(const float4*)(B + (size_t)(k0+br)*N + bcol + bc);
        }
        __syncthreads();
        #pragma unroll
        for (int kk = 0; kk < 16; kk++){
            float4 rm4 = *(const float4*)&As[kk][ty<<2];
            float4 rn4 = *(const float4*)&Bs[kk][tx<<2];
            float rm[4] = {rm4.x, rm4.y, rm4.z, rm4.w};
            float rn[4] = {rn4.x, rn4.y, rn4.z, rn4.w};
            #pragma unroll
            for (int m = 0; m < 4; m++)
                #pragma unroll
                for (int n = 0; n < 4; n++)
                    acc[m][n] = fmaf(rm[m], rn[n], acc[m][n]);
        }
        __syncthreads();
    }
    #pragma unroll
    for (int m = 0; m < 4; m++){
        int row  = brow + (ty<<2) + m;
        int col0 = bcol + (tx<<2);
        float4 o;
        o.x = acc[m][0]; o.y = acc[m][1]; o.z = acc[m][2]; o.w = acc[m][3];
        if (bias){ o.x += bias[col0]; o.y += bias[col0+1]; o.z += bias[col0+2]; o.w += bias[col0+3]; }
        *(float4*)(C + (size_t)row*N + col0) = o;
    }
}

__global__ void __launch_bounds__(256) k_gemm_h(const float* __restrict__ x, const float* __restrict__ Wg){
    sgemm_body(x, Wg, g_h, N_NODES, NG, D_INF, nullptr, 0);
}
__global__ void __launch_bounds__(256) k_gemm_xp(const float* __restrict__ Wih){
    sgemm_body(g_g, Wih, g_xproj, N_NODES, NG, HD, g_bias2, 1);
}
__global__ void __launch_bounds__(256) k_gemm_corr(float* __restrict__ out_corr){
    sgemm_body(g_xn, g_xn, out_corr, N_NODES, N_NODES, HD, nullptr, 1);
}

/* ------------------------ attention scalars a_src/a_dst --------------------- */
__global__ void k_attn(const float* __restrict__ att_src, const float* __restrict__ att_dst){
    int gt = blockIdx.x*blockDim.x + threadIdx.x;
    int w = gt >> 5, lane = gt & 31;
    if (w >= N_NODES*HEADS) return;
    int n = w >> 2, hh = w & 3;
    const float* hp = g_h + (size_t)n*NG + hh*HD;
    const float* as = att_src + hh*HD;
    const float* ad = att_dst + hh*HD;
    float s1 = 0.f, s2 = 0.f;
    #pragma unroll
    for (int q = 0; q < 4; q++){
        int dd = lane + q*32;
        float v = hp[dd];
        s1 = fmaf(v, as[dd], s1);
        s2 = fmaf(v, ad[dd], s2);
    }
    #pragma unroll
    for (int o = 16; o; o >>= 1){
        s1 += __shfl_xor_sync(0xffffffffu, s1, o);
        s2 += __shfl_xor_sync(0xffffffffu, s2, o);
    }
    if (lane == 0){ g_asrc[w] = s1; g_adst[w] = s2; }
}

/* ------------------------------ edge softmax -------------------------------- */
__global__ void k_edge_max(const int* __restrict__ ei){
    int i = blockIdx.x*blockDim.x + threadIdx.x;
    if (i >= ET*HEADS) return;
    int e = i >> 2, hh = i & 3;
    int s, d; edge_nodes(ei, e, s, d);
    float v = lrelu(g_asrc[s*HEADS+hh] + g_adst[d*HEADS+hh]);
    atomicMax(&g_menc[d*HEADS+hh], enc_f(v));
}
__global__ void k_edge_sum(const int* __restrict__ ei){
    int i = blockIdx.x*blockDim.x + threadIdx.x;
    if (i >= ET*HEADS) return;
    int e = i >> 2, hh = i & 3;
    int s, d; edge_nodes(ei, e, s, d);
    int idx = d*HEADS + hh;
    float v = lrelu(g_asrc[s*HEADS+hh] + g_adst[idx]);
    atomicAdd(&g_s[idx], __expf(v - dec_f(g_menc[idx])));
}
/* one warp per edge; mean-over-heads folded in (alpha * 0.25) */
__global__ void k_edge_agg(const int* __restrict__ ei){
    int gt = blockIdx.x*blockDim.x + threadIdx.x;
    int w = gt >> 5, lane = gt & 31;
    if (w >= ET) return;
    int s, d; edge_nodes(ei, w, s, d);
    float alpha[HEADS];
    #pragma unroll
    for (int hh = 0; hh < HEADS; hh++){
        float v = lrelu(g_asrc[s*HEADS+hh] + g_adst[d*HEADS+hh]);
        int idx = d*HEADS + hh;
        alpha[hh] = __expf(v - dec_f(g_menc[idx])) / (g_s[idx] + 1e-16f) * 0.25f;
    }
    const float* hpv = g_h + (size_t)s*NG;
    float* op = g_aggr + (size_t)d*HD;
    #pragma unroll
    for (int q = 0; q < 4; q++){
        int dd = lane + q*32;
        float val = alpha[0]*hpv[dd] + alpha[1]*hpv[HD+dd]
                  + alpha[2]*hpv[2*HD+dd] + alpha[3]*hpv[3*HD+dd];
        atomicAdd(op + dd, val);
    }
}
__global__ void k_gat_fin(const float* __restrict__ b_gat){
    int i = blockIdx.x*blockDim.x + threadIdx.x;
    if (i < N_NODES*HD) g_g[i] = fmaxf(g_aggr[i] + b_gat[i & (HD-1)], 0.f);
}
__global__ void k_bias2(const float* __restrict__ bi, const float* __restrict__ bh){
    int i = blockIdx.x*blockDim.x + threadIdx.x;
    if (i < NG) g_bias2[i] = bi[i] + bh[i];
}

/* -------------------- LSTM: 2-CTA cluster, weights in regs ------------------ */
/* CTA rank owns gate rows [rank*256, rank*256+256). 512 threads/CTA:
   thread tid -> row r_local = tid>>1 (+rank*256 global), half = tid&1 owns 64
   weights (32 packed f32x2 in regs; 64 regs, no spill at 512thr/128reg cap).
   CTA1 pushes its 256 pre-activation gates to CTA0 smem via DSMEM (release-
   arrive on mbarA). CTA0's 128 activation threads compute c,h, write h to both
   CTAs' smem (DSMEM push + release-arrive on mbarB in CTA1). */
__global__ void __launch_bounds__(512,1) __cluster_dims__(2,1,1)
k_lstm(const float* __restrict__ W_hh, float* __restrict__ out_emb)
{
    __shared__ __align__(16) float h_sh[HD];
    __shared__ float gates[NG];                       /* consumed in CTA0 only */
    __shared__ __align__(8) unsigned long long mbarA; /* CTA0: remote gates ready */
    __shared__ __align__(8) unsigned long long mbarB; /* CTA1: h ready           */

    const int tid  = threadIdx.x;
    const uint32_t rank = ctarank();
    const int r_local = tid >> 1;
    const int half    = tid & 1;
    const int rg      = (int)rank*256 + r_local;      /* global gate row */

    if (tid == 0){
        mbar_init(smem_u32(&mbarA), 256);
        mbar_init(smem_u32(&mbarB), 128);
    }
    if (tid < HD) h_sh[tid] = 0.f;
    __syncthreads();
    cluster_sync_();   /* peer mbarriers + h init visible before any DSMEM op */

    /* resident weights */
    unsigned long long wv[32];
    const unsigned long long* wp =
        (const unsigned long long*)(W_hh + (size_t)rg*HD + half*64);
    #pragma unroll
    for (int i = 0; i < 32; i++) wv[i] = wp[i];

    const unsigned long long* hp = (const unsigned long long*)h_sh + half*32;
    const uint32_t barA_l = smem_u32(&mbarA);
    const uint32_t barB_l = smem_u32(&mbarB);
    const uint32_t gates_rem = mapa_rank(smem_u32(&gates[256 + r_local]), 0);
    const uint32_t barA_rem  = mapa_rank(barA_l, 0);
    const uint32_t barB_rem  = mapa_rank(barB_l, 1);
    const uint32_t h_rem     = (tid < HD) ? mapa_rank(smem_u32(&h_sh[tid]), 1) : 0u;

    float cst = 0.f;
    float xp  = g_xproj[rg];      /* bias pre-folded into xproj by GEMM */

    for (int t = 0; t < N_NODES; t++){
        const uint32_t ph = (uint32_t)(t & 1);
        /* ---- 64-wide half-row dot: 32 f32x2 FMAs on register weights ---- */
        unsigned long long a0=0ull, a1=0ull, a2=0ull, a3=0ull;
        #pragma unroll
        for (int i = 0; i < 32; i += 4){
            unsigned long long h0 = hp[i+0], h1 = hp[i+1], h2 = hp[i+2], h3 = hp[i+3];
            FMA2(a0, wv[i+0], h0);
            FMA2(a1, wv[i+1], h1);
            FMA2(a2, wv[i+2], h2);
            FMA2(a3, wv[i+3], h3);
        }
        U64F2 u0, u1, u2, u3; u0.u=a0; u1.u=a1; u2.u=a2; u3.u=a3;
        float ssum = ((u0.f.x+u0.f.y)+(u1.f.x+u1.f.y))
                   + ((u2.f.x+u2.f.y)+(u3.f.x+u3.f.y));
        ssum += __shfl_xor_sync(0xffffffffu, ssum, 1);   /* pair-combine halves */
        float gate = xp + ssum;

        if (rank == 0){
            if (!half) gates[r_local] = gate;
            if (t+1 < N_NODES) xp = __ldg(&g_xproj[(size_t)(t+1)*NG + rg]);
            __syncthreads();                              /* local gates ready */
            if (tid < HD){
                mbar_wait_acq_cluster(barA_l, ph);        /* remote gates ready */
                float gi = gates[tid];
                float gf = gates[HD   + tid];
                float gg = gates[2*HD + tid];
                float go = gates[3*HD + tid];
                cst = fsigm(gf)*cst + fsigm(gi)*ftanh_(gg);
                float hn = fsigm(go)*ftanh_(cst);
                h_sh[tid] = hn;
                out_emb[(size_t)t*HD + tid] = hn;
                if (t+1 < N_NODES){
                    st_cluster_f32(h_rem, hn);            /* push h to CTA1 */
                    mbar_arrive_rel_cluster(barB_rem);
                }
            }
            __syncthreads();                              /* new local h ready */
        } else {
            if (!half){
                st_cluster_f32(gates_rem, gate);          /* push gate to CTA0 */
                mbar_arrive_rel_cluster(barA_rem);
            }
            if (t+1 < N_NODES){
                xp = __ldg(&g_xproj[(size_t)(t+1)*NG + rg]);
                mbar_wait_acq_cluster(barB_l, ph);        /* wait for h(t+1) */
            }
        }
    }
    cluster_sync_();
}

/* ------------------------------ normalize ----------------------------------- */
__global__ void k_norm(const float* __restrict__ emb){
    __shared__ float red[4];
    int t = blockIdx.x, d = threadIdx.x;       /* 128 threads */
    float v  = emb[(size_t)t*HD + d];
    float ss = v*v;
    #pragma unroll
    for (int o = 16; o; o >>= 1) ss += __shfl_xor_sync(0xffffffffu, ss, o);
    if ((d & 31) == 0) red[d >> 5] = ss;
    __syncthreads();
    float tot = red[0] + red[1] + red[2] + red[3];
    float inv = 1.f / fmaxf(sqrtf(tot), 1e-12f);
    g_xn[(size_t)t*HD + d] = v * inv;
}

/* --------------------------------- MLP -------------------------------------- */
__global__ void k_mlp(const float* __restrict__ emb,
                      const float* __restrict__ W1, const float* __restrict__ b1,
                      const float* __restrict__ W2, const float* __restrict__ b2,
                      float* __restrict__ mu, float* __restrict__ sg)
{
    __shared__ float xs[HD];
    __shared__ float hid[32];
    int t = blockIdx.x, tid = threadIdx.x;     /* 128 threads */
    xs[tid] = emb[(size_t)t*HD + tid];
    __syncthreads();
    if (tid < 32){
        float a = b1[tid];
        #pragma unroll 8
        for (int k = 0; k < HD; k++) a = fmaf(xs[k], W1[k*32 + tid], a);
        hid[tid] = fmaxf(a, 0.f);
    }
    __syncthreads();
    if (tid < 2){
        float a = b2[tid];
        #pragma unroll
        for (int k = 0; k < 32; k++) a = fmaf(hid[k], W2[k*2 + tid], a);
        if (tid == 0) mu[t] = a; else sg[t] = a;
    }
}

/* ------------------------------ launch -------------------------------------- */
extern "C" void kernel_launch(void* const* d_in, const int* in_sizes, int n_in,
                              void* d_out, int out_size)
{
    const float* x       = (const float*)d_in[0];
    const int*   ei      = (const int*  )d_in[1];
    const float* W_gat   = (const float*)d_in[2];
    const float* att_src = (const float*)d_in[3];
    const float* att_dst = (const float*)d_in[4];
    const float* b_gat   = (const float*)d_in[5];
    const float* W_ih    = (const float*)d_in[6];
    const float* W_hh    = (const float*)d_in[7];
    const float* b_ih    = (const float*)d_in[8];
    const float* b_hh    = (const float*)d_in[9];
    const float* W1      = (const float*)d_in[10];
    const float* b1      = (const float*)d_in[11];
    const float* W2      = (const float*)d_in[12];
    const float* b2      = (const float*)d_in[13];

    float* out      = (float*)d_out;
    float* out_emb  = out;
    float* out_corr = out + (size_t)N_NODES*HD;
    float* out_mu   = out_corr + (size_t)N_NODES*N_NODES;
    float* out_sg   = out_mu + N_NODES;

    k_init    <<<(N_NODES*HD + 255)/256, 256>>>();
    k_gemm_h  <<<dim3(NG/64, N_NODES/64), 256>>>(x, W_gat);
    k_attn    <<<(N_NODES*HEADS*32 + 255)/256, 256>>>(att_src, att_dst);
    k_edge_max<<<(ET*HEADS + 255)/256, 256>>>(ei);
    k_edge_sum<<<(ET*HEADS + 255)/256, 256>>>(ei);
    k_edge_agg<<<(ET*32    + 255)/256, 256>>>(ei);
    k_gat_fin <<<(N_NODES*HD + 255)/256, 256>>>(b_gat);
    k_bias2   <<<2, 256>>>(b_ih, b_hh);
    k_gemm_xp <<<dim3(NG/64, N_NODES/64), 256>>>(W_ih);
    k_lstm    <<<2, 512>>>(W_hh, out_emb);
    k_norm    <<<N_NODES, HD>>>(out_emb);
    k_gemm_corr<<<dim3(N_NODES/64, N_NODES/64), 256>>>(out_corr);
    k_mlp     <<<N_NODES, HD>>>(out_emb, W1, b1, W2, b2, out_mu, out_sg);
}